// round 1
// baseline (speedup 1.0000x reference)
#include <cuda_runtime.h>
#include <math.h>

// ---------------- problem constants ----------------
#define Bx   2
#define Sx   2048
#define Dx   2048
#define Hx   16
#define HDx  128
#define Ex   4
#define Ix   2048
#define Tx   (Bx * Sx)          // 4096 tokens

// ---------------- scratch (static device globals; no runtime alloc) ----------------
__device__ float g_x1  [(size_t)Tx * Dx];   // LN1 output
__device__ float g_q   [(size_t)Tx * Dx];
__device__ float g_k   [(size_t)Tx * Dx];
__device__ float g_v   [(size_t)Tx * Dx];
__device__ float g_attn[(size_t)Tx * Dx];
__device__ float g_x2  [(size_t)Tx * Dx];   // LN2 output
__device__ float g_hmid[(size_t)Tx * Ix];   // expert mid activations (reused per expert)
__device__ float g_comb[Tx * Ex];           // dense combine weights

// ---------------- LayerNorm: one block (256 thr) per row of 2048 ----------------
__global__ __launch_bounds__(256) void ln_kernel(
    const float* __restrict__ x, const float* __restrict__ w,
    const float* __restrict__ b, float* __restrict__ y)
{
    __shared__ float red[8];
    int row = blockIdx.x;
    int t = threadIdx.x;
    const float* xr = x + (size_t)row * Dx;

    float v[8];
    float s = 0.f;
#pragma unroll
    for (int i = 0; i < 8; i++) { v[i] = xr[t + i * 256]; s += v[i]; }
#pragma unroll
    for (int off = 16; off >= 1; off >>= 1) s += __shfl_xor_sync(0xffffffffu, s, off);
    if ((t & 31) == 0) red[t >> 5] = s;
    __syncthreads();
    float tot = red[0] + red[1] + red[2] + red[3] + red[4] + red[5] + red[6] + red[7];
    float mu = tot * (1.0f / (float)Dx);

    float s2 = 0.f;
#pragma unroll
    for (int i = 0; i < 8; i++) { float d = v[i] - mu; s2 += d * d; }
    __syncthreads();
#pragma unroll
    for (int off = 16; off >= 1; off >>= 1) s2 += __shfl_xor_sync(0xffffffffu, s2, off);
    if ((t & 31) == 0) red[t >> 5] = s2;
    __syncthreads();
    float tot2 = red[0] + red[1] + red[2] + red[3] + red[4] + red[5] + red[6] + red[7];
    float var = tot2 * (1.0f / (float)Dx);
    float r = rsqrtf(var + 1e-5f);

    float* yr = y + (size_t)row * Dx;
#pragma unroll
    for (int i = 0; i < 8; i++) {
        int c = t + i * 256;
        yr[c] = (v[i] - mu) * r * w[c] + b[c];
    }
}

// ---------------- tiled fp32 GEMM: C[M,N] = A[M,K] @ B[K,N] (+epilogue) ----------------
// MODE 0: C = AB + bias
// MODE 1: C = AB + bias + extra   (extra is [M,N] residual)
// MODE 2: C = gelu_exact(AB + bias)
// MODE 3: C += extra[m*4] * (AB + bias)   (extra = comb + e, row stride Ex=4)
#define BM 128
#define BN 128
#define BK 16

template <int MODE>
__global__ __launch_bounds__(256, 2) void gemm_k(
    const float* __restrict__ A, const float* __restrict__ B,
    const float* __restrict__ bias, float* __restrict__ C,
    const float* __restrict__ extra, int M, int N, int K)
{
    __shared__ float As[BK][BM];
    __shared__ float Bs[BK][BN];

    const int tid = threadIdx.x;
    const int tx = tid & 15;
    const int ty = tid >> 4;
    const int m0 = blockIdx.y * BM;
    const int n0 = blockIdx.x * BN;

    float acc[8][8];
#pragma unroll
    for (int i = 0; i < 8; i++)
#pragma unroll
        for (int j = 0; j < 8; j++) acc[i][j] = 0.f;

    // A loader: 512 float4 per tile; thread handles f = tid, tid+256
    const int arow = tid >> 2;            // 0..63
    const int akq  = (tid & 3) * 4;       // k offset within tile
    // B loader: krow = f>>5, nc = (f&31)*4
    const int bkr = tid >> 5;             // 0..7
    const int bnc = (tid & 31) * 4;

    const float* Ap = A + (size_t)m0 * K;
    const float* Bp = B + n0;

    for (int k0 = 0; k0 < K; k0 += BK) {
#pragma unroll
        for (int u = 0; u < 2; u++) {
            int row = arow + u * 64;
            float4 av = *(const float4*)(Ap + (size_t)row * K + k0 + akq);
            As[akq + 0][row] = av.x;
            As[akq + 1][row] = av.y;
            As[akq + 2][row] = av.z;
            As[akq + 3][row] = av.w;
        }
#pragma unroll
        for (int u = 0; u < 2; u++) {
            int kr = bkr + u * 8;
            float4 bv = *(const float4*)(Bp + (size_t)(k0 + kr) * N + bnc);
            *(float4*)&Bs[kr][bnc] = bv;
        }
        __syncthreads();

#pragma unroll
        for (int kk = 0; kk < BK; kk++) {
            float4 a0 = *(const float4*)&As[kk][ty * 8];
            float4 a1 = *(const float4*)&As[kk][ty * 8 + 4];
            float4 b0 = *(const float4*)&Bs[kk][tx * 8];
            float4 b1 = *(const float4*)&Bs[kk][tx * 8 + 4];
            float a[8] = {a0.x, a0.y, a0.z, a0.w, a1.x, a1.y, a1.z, a1.w};
            float b[8] = {b0.x, b0.y, b0.z, b0.w, b1.x, b1.y, b1.z, b1.w};
#pragma unroll
            for (int i = 0; i < 8; i++)
#pragma unroll
                for (int j = 0; j < 8; j++)
                    acc[i][j] = fmaf(a[i], b[j], acc[i][j]);
        }
        __syncthreads();
    }

#pragma unroll
    for (int i = 0; i < 8; i++) {
        int gm = m0 + ty * 8 + i;
        float* crow = C + (size_t)gm * N + n0 + tx * 8;
        float scale = 0.f;
        if (MODE == 3) scale = extra[(size_t)gm * Ex];
#pragma unroll
        for (int j = 0; j < 8; j++) {
            int gn = n0 + tx * 8 + j;
            float val = acc[i][j] + bias[gn];
            if (MODE == 1) val += extra[(size_t)gm * N + gn];
            if (MODE == 2) val = 0.5f * val * (1.0f + erff(val * 0.70710678118654752f));
            if (MODE == 3) crow[j] += scale * val;
            else           crow[j] = val;
        }
    }
}

// ---------------- RoPE over q and k in-place ----------------
__global__ __launch_bounds__(256) void rope_kernel(float* __restrict__ q, float* __restrict__ k)
{
    int idx = blockIdx.x * 256 + threadIdx.x;          // Tx*Hx*64
    int d = idx & 63;
    int rest = idx >> 6;
    int h = rest & (Hx - 1);
    int tok = rest >> 4;
    int s = tok & (Sx - 1);

    // inv_freq = 10000^(-d/64)
    float freq = expf(-(float)d * (9.21034037197618f / 64.0f));
    float ang = (float)s * freq;
    float c, sn;
    sincosf(ang, &sn, &c);

    size_t base = (size_t)tok * Dx + h * HDx;
    float q1 = q[base + d], q2 = q[base + d + 64];
    q[base + d]      = q1 * c - q2 * sn;
    q[base + d + 64] = q2 * c + q1 * sn;
    float k1 = k[base + d], k2 = k[base + d + 64];
    k[base + d]      = k1 * c - k2 * sn;
    k[base + d + 64] = k2 * c + k1 * sn;
}

// ---------------- causal attention: one warp per query row, online softmax ----------------
__global__ __launch_bounds__(256) void attn_kernel(
    const float* __restrict__ q, const float* __restrict__ k,
    const float* __restrict__ v, float* __restrict__ o)
{
    int bh = blockIdx.x;                 // b*H + h
    int b = bh >> 4;
    int h = bh & (Hx - 1);
    int warp = threadIdx.x >> 5;
    int lane = threadIdx.x & 31;
    int qi = blockIdx.y * 8 + warp;

    size_t qoff = ((size_t)(b * Sx + qi)) * Dx + h * HDx + lane * 4;
    float4 q4 = *(const float4*)(q + qoff);
    const float scale = 0.0883883476483184f;   // 1/sqrt(128)
    q4.x *= scale; q4.y *= scale; q4.z *= scale; q4.w *= scale;

    const float* kb = k + ((size_t)b * Sx) * Dx + h * HDx + lane * 4;
    const float* vb = v + ((size_t)b * Sx) * Dx + h * HDx + lane * 4;

    float m = -1e30f, l = 0.f;
    float4 acc = make_float4(0.f, 0.f, 0.f, 0.f);

    for (int j = 0; j <= qi; j++) {
        float4 k4 = *(const float4*)(kb + (size_t)j * Dx);
        float s = q4.x * k4.x + q4.y * k4.y + q4.z * k4.z + q4.w * k4.w;
        s += __shfl_xor_sync(0xffffffffu, s, 16);
        s += __shfl_xor_sync(0xffffffffu, s, 8);
        s += __shfl_xor_sync(0xffffffffu, s, 4);
        s += __shfl_xor_sync(0xffffffffu, s, 2);
        s += __shfl_xor_sync(0xffffffffu, s, 1);
        float4 v4 = *(const float4*)(vb + (size_t)j * Dx);
        float nm = fmaxf(m, s);
        float corr = __expf(m - nm);
        float p = __expf(s - nm);
        l = l * corr + p;
        acc.x = fmaf(acc.x, corr, p * v4.x);
        acc.y = fmaf(acc.y, corr, p * v4.y);
        acc.z = fmaf(acc.z, corr, p * v4.z);
        acc.w = fmaf(acc.w, corr, p * v4.w);
        m = nm;
    }
    float inv = __fdividef(1.0f, l);
    float4 outv = make_float4(acc.x * inv, acc.y * inv, acc.z * inv, acc.w * inv);
    *(float4*)(o + qoff) = outv;
}

// ---------------- MoE gate: softmax -> top-2 -> softmax(top vals) -> dense comb ----------------
__global__ __launch_bounds__(256) void gate_kernel(
    const float* __restrict__ x, const float* __restrict__ wg, float* __restrict__ comb)
{
    int warp = threadIdx.x >> 5;
    int lane = threadIdx.x & 31;
    int t = blockIdx.x * 8 + warp;
    const float* xr = x + (size_t)t * Dx;

    float a0 = 0.f, a1 = 0.f, a2 = 0.f, a3 = 0.f;
    for (int d = lane; d < Dx; d += 32) {
        float xv = xr[d];
        float4 w4 = ((const float4*)wg)[d];   // wg is [D,4] row-major
        a0 = fmaf(xv, w4.x, a0);
        a1 = fmaf(xv, w4.y, a1);
        a2 = fmaf(xv, w4.z, a2);
        a3 = fmaf(xv, w4.w, a3);
    }
#pragma unroll
    for (int off = 16; off >= 1; off >>= 1) {
        a0 += __shfl_xor_sync(0xffffffffu, a0, off);
        a1 += __shfl_xor_sync(0xffffffffu, a1, off);
        a2 += __shfl_xor_sync(0xffffffffu, a2, off);
        a3 += __shfl_xor_sync(0xffffffffu, a3, off);
    }
    if (lane == 0) {
        float lg[4] = {a0, a1, a2, a3};
        float mx = fmaxf(fmaxf(lg[0], lg[1]), fmaxf(lg[2], lg[3]));
        float e[4], sum = 0.f;
#pragma unroll
        for (int i = 0; i < 4; i++) { e[i] = expf(lg[i] - mx); sum += e[i]; }
        float p[4];
#pragma unroll
        for (int i = 0; i < 4; i++) p[i] = e[i] / sum;

        int i0 = 0;
#pragma unroll
        for (int i = 1; i < 4; i++) if (p[i] > p[i0]) i0 = i;
        int i1 = (i0 == 0) ? 1 : 0;
#pragma unroll
        for (int i = 0; i < 4; i++) if (i != i0 && p[i] > p[i1]) i1 = i;

        // renormalize: softmax over the two top probabilities
        float hi = fmaxf(p[i0], p[i1]);
        float ea = expf(p[i0] - hi), eb = expf(p[i1] - hi);
        float inv = 1.0f / (ea + eb);
        float w0 = ea * inv, w1 = eb * inv;
#pragma unroll
        for (int i = 0; i < 4; i++)
            comb[t * 4 + i] = (i == i0) ? w0 : ((i == i1) ? w1 : 0.f);
    }
}

// ---------------- host launcher ----------------
extern "C" void kernel_launch(void* const* d_in, const int* in_sizes, int n_in,
                              void* d_out, int out_size)
{
    const float* hidden = (const float*)d_in[0];
    const float* wq   = (const float*)d_in[1];
    const float* bq   = (const float*)d_in[2];
    const float* wk   = (const float*)d_in[3];
    const float* bk   = (const float*)d_in[4];
    const float* wv   = (const float*)d_in[5];
    const float* bv   = (const float*)d_in[6];
    const float* wo   = (const float*)d_in[7];
    const float* bo   = (const float*)d_in[8];
    const float* ln1w = (const float*)d_in[9];
    const float* ln1b = (const float*)d_in[10];
    const float* ln2w = (const float*)d_in[11];
    const float* ln2b = (const float*)d_in[12];
    const float* wgate= (const float*)d_in[13];
    const float* we1  = (const float*)d_in[14];
    const float* be1  = (const float*)d_in[15];
    const float* we2  = (const float*)d_in[16];
    const float* be2  = (const float*)d_in[17];
    float* out = (float*)d_out;

    float *x1, *q, *k, *v, *attn, *x2, *hmid, *comb;
    cudaGetSymbolAddress((void**)&x1,   g_x1);
    cudaGetSymbolAddress((void**)&q,    g_q);
    cudaGetSymbolAddress((void**)&k,    g_k);
    cudaGetSymbolAddress((void**)&v,    g_v);
    cudaGetSymbolAddress((void**)&attn, g_attn);
    cudaGetSymbolAddress((void**)&x2,   g_x2);
    cudaGetSymbolAddress((void**)&hmid, g_hmid);
    cudaGetSymbolAddress((void**)&comb, g_comb);

    dim3 gg(Dx / BN, Tx / BM);          // (16, 32)

    // 1) LN1
    ln_kernel<<<Tx, 256>>>(hidden, ln1w, ln1b, x1);
    // 2) QKV projections
    gemm_k<0><<<gg, 256>>>(x1, wq, bq, q, nullptr, Tx, Dx, Dx);
    gemm_k<0><<<gg, 256>>>(x1, wk, bk, k, nullptr, Tx, Dx, Dx);
    gemm_k<0><<<gg, 256>>>(x1, wv, bv, v, nullptr, Tx, Dx, Dx);
    // 3) RoPE in-place on q, k
    rope_kernel<<<(Tx * Hx * 64) / 256, 256>>>(q, k);
    // 4) causal attention
    attn_kernel<<<dim3(Bx * Hx, Sx / 8), 256>>>(q, k, v, attn);
    // 5) O-projection + residual  ->  d_out holds h = x + Attn(LN1(x))
    gemm_k<1><<<gg, 256>>>(attn, wo, bo, out, hidden, Tx, Dx, Dx);
    // 6) LN2
    ln_kernel<<<Tx, 256>>>(out, ln2w, ln2b, x2);
    // 7) gate -> dense combine weights
    gate_kernel<<<Tx / 8, 256>>>(x2, wgate, comb);
    // 8) dense per-expert MLPs, comb-weighted accumulate into d_out
    for (int e = 0; e < Ex; e++) {
        gemm_k<2><<<dim3(Ix / BN, Tx / BM), 256>>>(
            x2, we1 + (size_t)e * Dx * Ix, be1 + (size_t)e * Ix,
            hmid, nullptr, Tx, Ix, Dx);
        gemm_k<3><<<gg, 256>>>(
            hmid, we2 + (size_t)e * Ix * Dx, be2 + (size_t)e * Dx,
            out, comb + e, Tx, Dx, Ix);
    }
}

// round 2
// speedup vs baseline: 1.0027x; 1.0027x over previous
#include <cuda_runtime.h>
#include <math.h>

// ---------------- problem constants ----------------
#define Bx   2
#define Sx   2048
#define Dx   2048
#define Hx   16
#define HDx  128
#define Ex   4
#define Ix   2048
#define Tx   (Bx * Sx)          // 4096 tokens

// ---------------- scratch (static device globals; no runtime alloc) ----------------
__device__ float g_x1  [(size_t)Tx * Dx];   // LN1 output
__device__ float g_q   [(size_t)Tx * Dx];
__device__ float g_k   [(size_t)Tx * Dx];
__device__ float g_v   [(size_t)Tx * Dx];
__device__ float g_attn[(size_t)Tx * Dx];
__device__ float g_x2  [(size_t)Tx * Dx];   // LN2 output
__device__ float g_hmid[(size_t)Tx * Ix];   // expert mid activations (reused per expert)
__device__ float g_comb[Tx * Ex];           // dense combine weights

// ---------------- LayerNorm: one block (256 thr) per row of 2048 ----------------
__global__ __launch_bounds__(256) void ln_kernel(
    const float* __restrict__ x, const float* __restrict__ w,
    const float* __restrict__ b, float* __restrict__ y)
{
    __shared__ float red[8];
    int row = blockIdx.x;
    int t = threadIdx.x;
    const float* xr = x + (size_t)row * Dx;

    float v[8];
    float s = 0.f;
#pragma unroll
    for (int i = 0; i < 8; i++) { v[i] = xr[t + i * 256]; s += v[i]; }
#pragma unroll
    for (int off = 16; off >= 1; off >>= 1) s += __shfl_xor_sync(0xffffffffu, s, off);
    if ((t & 31) == 0) red[t >> 5] = s;
    __syncthreads();
    float tot = red[0] + red[1] + red[2] + red[3] + red[4] + red[5] + red[6] + red[7];
    float mu = tot * (1.0f / (float)Dx);

    float s2 = 0.f;
#pragma unroll
    for (int i = 0; i < 8; i++) { float d = v[i] - mu; s2 += d * d; }
    __syncthreads();
#pragma unroll
    for (int off = 16; off >= 1; off >>= 1) s2 += __shfl_xor_sync(0xffffffffu, s2, off);
    if ((t & 31) == 0) red[t >> 5] = s2;
    __syncthreads();
    float tot2 = red[0] + red[1] + red[2] + red[3] + red[4] + red[5] + red[6] + red[7];
    float var = tot2 * (1.0f / (float)Dx);
    float r = rsqrtf(var + 1e-5f);

    float* yr = y + (size_t)row * Dx;
#pragma unroll
    for (int i = 0; i < 8; i++) {
        int c = t + i * 256;
        yr[c] = (v[i] - mu) * r * w[c] + b[c];
    }
}

// ---------------- tiled fp32 GEMM: C[M,N] = A[M,K] @ B[K,N] (+epilogue) ----------------
// MODE 0: C = AB + bias
// MODE 1: C = AB + bias + extra   (extra is [M,N] residual)
// MODE 2: C = gelu_exact(AB + bias)
// MODE 3: C += extra[m*4] * (AB + bias)   (extra = comb + e, row stride Ex=4)
#define BM 128
#define BN 128
#define BK 16

template <int MODE>
__global__ __launch_bounds__(256, 2) void gemm_k(
    const float* __restrict__ A, const float* __restrict__ B,
    const float* __restrict__ bias, float* __restrict__ C,
    const float* __restrict__ extra, int M, int N, int K)
{
    __shared__ float As[BK][BM];
    __shared__ float Bs[BK][BN];

    const int tid = threadIdx.x;
    const int tx = tid & 15;
    const int ty = tid >> 4;
    const int m0 = blockIdx.y * BM;
    const int n0 = blockIdx.x * BN;

    float acc[8][8];
#pragma unroll
    for (int i = 0; i < 8; i++)
#pragma unroll
        for (int j = 0; j < 8; j++) acc[i][j] = 0.f;

    // A loader: 512 float4 per tile; thread handles f = tid, tid+256
    const int arow = tid >> 2;            // 0..63
    const int akq  = (tid & 3) * 4;       // k offset within tile
    // B loader: krow = f>>5, nc = (f&31)*4
    const int bkr = tid >> 5;             // 0..7
    const int bnc = (tid & 31) * 4;

    const float* Ap = A + (size_t)m0 * K;
    const float* Bp = B + n0;

    for (int k0 = 0; k0 < K; k0 += BK) {
#pragma unroll
        for (int u = 0; u < 2; u++) {
            int row = arow + u * 64;
            float4 av = *(const float4*)(Ap + (size_t)row * K + k0 + akq);
            As[akq + 0][row] = av.x;
            As[akq + 1][row] = av.y;
            As[akq + 2][row] = av.z;
            As[akq + 3][row] = av.w;
        }
#pragma unroll
        for (int u = 0; u < 2; u++) {
            int kr = bkr + u * 8;
            float4 bv = *(const float4*)(Bp + (size_t)(k0 + kr) * N + bnc);
            *(float4*)&Bs[kr][bnc] = bv;
        }
        __syncthreads();

#pragma unroll
        for (int kk = 0; kk < BK; kk++) {
            float4 a0 = *(const float4*)&As[kk][ty * 8];
            float4 a1 = *(const float4*)&As[kk][ty * 8 + 4];
            float4 b0 = *(const float4*)&Bs[kk][tx * 8];
            float4 b1 = *(const float4*)&Bs[kk][tx * 8 + 4];
            float a[8] = {a0.x, a0.y, a0.z, a0.w, a1.x, a1.y, a1.z, a1.w};
            float b[8] = {b0.x, b0.y, b0.z, b0.w, b1.x, b1.y, b1.z, b1.w};
#pragma unroll
            for (int i = 0; i < 8; i++)
#pragma unroll
                for (int j = 0; j < 8; j++)
                    acc[i][j] = fmaf(a[i], b[j], acc[i][j]);
        }
        __syncthreads();
    }

#pragma unroll
    for (int i = 0; i < 8; i++) {
        int gm = m0 + ty * 8 + i;
        float* crow = C + (size_t)gm * N + n0 + tx * 8;
        float scale = 0.f;
        if (MODE == 3) scale = extra[(size_t)gm * Ex];
#pragma unroll
        for (int j = 0; j < 8; j++) {
            int gn = n0 + tx * 8 + j;
            float val = acc[i][j] + bias[gn];
            if (MODE == 1) val += extra[(size_t)gm * N + gn];
            if (MODE == 2) val = 0.5f * val * (1.0f + erff(val * 0.70710678118654752f));
            if (MODE == 3) crow[j] += scale * val;
            else           crow[j] = val;
        }
    }
}

// ---------------- RoPE over q and k in-place ----------------
__global__ __launch_bounds__(256) void rope_kernel(float* __restrict__ q, float* __restrict__ k)
{
    int idx = blockIdx.x * 256 + threadIdx.x;          // Tx*Hx*64
    int d = idx & 63;
    int rest = idx >> 6;
    int h = rest & (Hx - 1);
    int tok = rest >> 4;
    int s = tok & (Sx - 1);

    // inv_freq = 10000^(-d/64)
    float freq = expf(-(float)d * (9.21034037197618f / 64.0f));
    float ang = (float)s * freq;
    float c, sn;
    sincosf(ang, &sn, &c);

    size_t base = (size_t)tok * Dx + h * HDx;
    float q1 = q[base + d], q2 = q[base + d + 64];
    q[base + d]      = q1 * c - q2 * sn;
    q[base + d + 64] = q2 * c + q1 * sn;
    float k1 = k[base + d], k2 = k[base + d + 64];
    k[base + d]      = k1 * c - k2 * sn;
    k[base + d + 64] = k2 * c + k1 * sn;
}

// ---------------- causal attention: one warp per query row, online softmax ----------------
__global__ __launch_bounds__(256) void attn_kernel(
    const float* __restrict__ q, const float* __restrict__ k,
    const float* __restrict__ v, float* __restrict__ o)
{
    int bh = blockIdx.x;                 // b*H + h
    int b = bh >> 4;
    int h = bh & (Hx - 1);
    int warp = threadIdx.x >> 5;
    int lane = threadIdx.x & 31;
    int qi = blockIdx.y * 8 + warp;

    size_t qoff = ((size_t)(b * Sx + qi)) * Dx + h * HDx + lane * 4;
    float4 q4 = *(const float4*)(q + qoff);
    const float scale = 0.0883883476483184f;   // 1/sqrt(128)
    q4.x *= scale; q4.y *= scale; q4.z *= scale; q4.w *= scale;

    const float* kb = k + ((size_t)b * Sx) * Dx + h * HDx + lane * 4;
    const float* vb = v + ((size_t)b * Sx) * Dx + h * HDx + lane * 4;

    float m = -1e30f, l = 0.f;
    float4 acc = make_float4(0.f, 0.f, 0.f, 0.f);

    for (int j = 0; j <= qi; j++) {
        float4 k4 = *(const float4*)(kb + (size_t)j * Dx);
        float s = q4.x * k4.x + q4.y * k4.y + q4.z * k4.z + q4.w * k4.w;
        s += __shfl_xor_sync(0xffffffffu, s, 16);
        s += __shfl_xor_sync(0xffffffffu, s, 8);
        s += __shfl_xor_sync(0xffffffffu, s, 4);
        s += __shfl_xor_sync(0xffffffffu, s, 2);
        s += __shfl_xor_sync(0xffffffffu, s, 1);
        float4 v4 = *(const float4*)(vb + (size_t)j * Dx);
        float nm = fmaxf(m, s);
        float corr = __expf(m - nm);
        float p = __expf(s - nm);
        l = l * corr + p;
        acc.x = fmaf(acc.x, corr, p * v4.x);
        acc.y = fmaf(acc.y, corr, p * v4.y);
        acc.z = fmaf(acc.z, corr, p * v4.z);
        acc.w = fmaf(acc.w, corr, p * v4.w);
        m = nm;
    }
    float inv = __fdividef(1.0f, l);
    float4 outv = make_float4(acc.x * inv, acc.y * inv, acc.z * inv, acc.w * inv);
    *(float4*)(o + qoff) = outv;
}

// ---------------- MoE gate: softmax -> top-2 -> softmax(top vals) -> dense comb ----------------
__global__ __launch_bounds__(256) void gate_kernel(
    const float* __restrict__ x, const float* __restrict__ wg, float* __restrict__ comb)
{
    int warp = threadIdx.x >> 5;
    int lane = threadIdx.x & 31;
    int t = blockIdx.x * 8 + warp;
    const float* xr = x + (size_t)t * Dx;

    float a0 = 0.f, a1 = 0.f, a2 = 0.f, a3 = 0.f;
    for (int d = lane; d < Dx; d += 32) {
        float xv = xr[d];
        float4 w4 = ((const float4*)wg)[d];   // wg is [D,4] row-major
        a0 = fmaf(xv, w4.x, a0);
        a1 = fmaf(xv, w4.y, a1);
        a2 = fmaf(xv, w4.z, a2);
        a3 = fmaf(xv, w4.w, a3);
    }
#pragma unroll
    for (int off = 16; off >= 1; off >>= 1) {
        a0 += __shfl_xor_sync(0xffffffffu, a0, off);
        a1 += __shfl_xor_sync(0xffffffffu, a1, off);
        a2 += __shfl_xor_sync(0xffffffffu, a2, off);
        a3 += __shfl_xor_sync(0xffffffffu, a3, off);
    }
    if (lane == 0) {
        float lg[4] = {a0, a1, a2, a3};
        float mx = fmaxf(fmaxf(lg[0], lg[1]), fmaxf(lg[2], lg[3]));
        float e[4], sum = 0.f;
#pragma unroll
        for (int i = 0; i < 4; i++) { e[i] = expf(lg[i] - mx); sum += e[i]; }
        float p[4];
#pragma unroll
        for (int i = 0; i < 4; i++) p[i] = e[i] / sum;

        int i0 = 0;
#pragma unroll
        for (int i = 1; i < 4; i++) if (p[i] > p[i0]) i0 = i;
        int i1 = (i0 == 0) ? 1 : 0;
#pragma unroll
        for (int i = 0; i < 4; i++) if (i != i0 && p[i] > p[i1]) i1 = i;

        // renormalize: softmax over the two top probabilities
        float hi = fmaxf(p[i0], p[i1]);
        float ea = expf(p[i0] - hi), eb = expf(p[i1] - hi);
        float inv = 1.0f / (ea + eb);
        float w0 = ea * inv, w1 = eb * inv;
#pragma unroll
        for (int i = 0; i < 4; i++)
            comb[t * 4 + i] = (i == i0) ? w0 : ((i == i1) ? w1 : 0.f);
    }
}

// ---------------- host launcher ----------------
extern "C" void kernel_launch(void* const* d_in, const int* in_sizes, int n_in,
                              void* d_out, int out_size)
{
    const float* hidden = (const float*)d_in[0];
    const float* wq   = (const float*)d_in[1];
    const float* bq   = (const float*)d_in[2];
    const float* wk   = (const float*)d_in[3];
    const float* bk   = (const float*)d_in[4];
    const float* wv   = (const float*)d_in[5];
    const float* bv   = (const float*)d_in[6];
    const float* wo   = (const float*)d_in[7];
    const float* bo   = (const float*)d_in[8];
    const float* ln1w = (const float*)d_in[9];
    const float* ln1b = (const float*)d_in[10];
    const float* ln2w = (const float*)d_in[11];
    const float* ln2b = (const float*)d_in[12];
    const float* wgate= (const float*)d_in[13];
    const float* we1  = (const float*)d_in[14];
    const float* be1  = (const float*)d_in[15];
    const float* we2  = (const float*)d_in[16];
    const float* be2  = (const float*)d_in[17];
    float* out = (float*)d_out;

    float *x1, *q, *k, *v, *attn, *x2, *hmid, *comb;
    cudaGetSymbolAddress((void**)&x1,   g_x1);
    cudaGetSymbolAddress((void**)&q,    g_q);
    cudaGetSymbolAddress((void**)&k,    g_k);
    cudaGetSymbolAddress((void**)&v,    g_v);
    cudaGetSymbolAddress((void**)&attn, g_attn);
    cudaGetSymbolAddress((void**)&x2,   g_x2);
    cudaGetSymbolAddress((void**)&hmid, g_hmid);
    cudaGetSymbolAddress((void**)&comb, g_comb);

    dim3 gg(Dx / BN, Tx / BM);          // (16, 32)

    // 1) LN1
    ln_kernel<<<Tx, 256>>>(hidden, ln1w, ln1b, x1);
    // 2) QKV projections
    gemm_k<0><<<gg, 256>>>(x1, wq, bq, q, nullptr, Tx, Dx, Dx);
    gemm_k<0><<<gg, 256>>>(x1, wk, bk, k, nullptr, Tx, Dx, Dx);
    gemm_k<0><<<gg, 256>>>(x1, wv, bv, v, nullptr, Tx, Dx, Dx);
    // 3) RoPE in-place on q, k
    rope_kernel<<<(Tx * Hx * 64) / 256, 256>>>(q, k);
    // 4) causal attention
    attn_kernel<<<dim3(Bx * Hx, Sx / 8), 256>>>(q, k, v, attn);
    // 5) O-projection + residual  ->  d_out holds h = x + Attn(LN1(x))
    gemm_k<1><<<gg, 256>>>(attn, wo, bo, out, hidden, Tx, Dx, Dx);
    // 6) LN2
    ln_kernel<<<Tx, 256>>>(out, ln2w, ln2b, x2);
    // 7) gate -> dense combine weights
    gate_kernel<<<Tx / 8, 256>>>(x2, wgate, comb);
    // 8) dense per-expert MLPs, comb-weighted accumulate into d_out
    for (int e = 0; e < Ex; e++) {
        gemm_k<2><<<dim3(Ix / BN, Tx / BM), 256>>>(
            x2, we1 + (size_t)e * Dx * Ix, be1 + (size_t)e * Ix,
            hmid, nullptr, Tx, Ix, Dx);
        gemm_k<3><<<gg, 256>>>(
            hmid, we2 + (size_t)e * Ix * Dx, be2 + (size_t)e * Dx,
            out, comb + e, Tx, Dx, Ix);
    }
}